// round 6
// baseline (speedup 1.0000x reference)
#include <cuda_runtime.h>
#include <math.h>

#define Bsz 4
#define Tt  4096
#define Cc  1024
#define Hh  64
#define BT  (Bsz*Tt)

// bf16 hi/lo pair arrays: [token][32] u32, each u32 = (bf16 even-h | bf16 odd-h << 16)
__device__ unsigned g_qh[BT*32];
__device__ unsigned g_ql[BT*32];
__device__ unsigned g_kh[BT*32];
__device__ unsigned g_kl[BT*32];
__device__ unsigned g_vh[BT*32];
__device__ unsigned g_vl[BT*32];

// ---------------------------------------------------------------------------
// helpers
// ---------------------------------------------------------------------------
__device__ __forceinline__ void mma16816(float c[4], unsigned a0, unsigned a1,
                                         unsigned a2, unsigned a3,
                                         unsigned b0, unsigned b1) {
    asm volatile(
        "mma.sync.aligned.m16n8k16.row.col.f32.bf16.bf16.f32 "
        "{%0,%1,%2,%3}, {%4,%5,%6,%7}, {%8,%9}, {%0,%1,%2,%3};\n"
        : "+f"(c[0]), "+f"(c[1]), "+f"(c[2]), "+f"(c[3])
        : "r"(a0), "r"(a1), "r"(a2), "r"(a3), "r"(b0), "r"(b1));
}

// pack two fp32 into bf16x2 by truncation (low half = x, high half = y)
__device__ __forceinline__ unsigned pack_hi(float x, float y) {
    return (__float_as_uint(x) >> 16) | (__float_as_uint(y) & 0xFFFF0000u);
}
__device__ __forceinline__ float trunc_bf(float x) {
    return __uint_as_float(__float_as_uint(x) & 0xFFFF0000u);
}
// round-to-nearest bf16x2 pack (low = x, high = y)
__device__ __forceinline__ unsigned pack_rn(float x, float y) {
    unsigned r;
    asm("cvt.rn.bf16x2.f32 %0, %1, %2;" : "=r"(r) : "f"(y), "f"(x));
    return r;
}

// ---------------------------------------------------------------------------
// Kernel 1: QKV projection.  [16384,1024] @ [1024,64] -> bf16 hi/lo pairs.
// CTA: 256 thr / 8 warps, tile M=128 (16 rows/warp), N=64, K-chunk 16.
// Split-bf16: acc = Ah*Bh + Al*Bh + Ah*Bl.
// ---------------------------------------------------------------------------
__global__ __launch_bounds__(256) void qkv_gemm(const float* __restrict__ x,
                                                const float* __restrict__ Wq,
                                                const float* __restrict__ Wk,
                                                const float* __restrict__ Wv) {
    __shared__ unsigned Xh[128][12], Xl[128][12];   // [row][k-pair 0..7], pad 12
    __shared__ unsigned Wph[8][72], Wpl[8][72];     // [k-pair][n], pad 72

    const int which = blockIdx.y;
    const float* __restrict__ W = (which == 0) ? Wq : (which == 1) ? Wk : Wv;
    unsigned* __restrict__ OH = (which == 0) ? g_qh : (which == 1) ? g_kh : g_vh;
    unsigned* __restrict__ OL = (which == 0) ? g_ql : (which == 1) ? g_kl : g_vl;

    const int m0   = blockIdx.x * 128;
    const int tid  = threadIdx.x;
    const int w    = tid >> 5;
    const int lane = tid & 31;
    const int gid  = lane >> 2;
    const int tig  = lane & 3;

    const int xrow = tid >> 2;          // 0..63
    const int xkq  = tid & 3;           // float4 group within 16-k chunk
    const int wkk  = tid >> 4;          // k-pair 0..7 (tid < 128)
    const int wn   = (tid & 15) * 4;    // n 0..60

    float acc[8][4];
    #pragma unroll
    for (int j = 0; j < 8; j++)
        #pragma unroll
        for (int e = 0; e < 4; e++) acc[j][e] = 0.f;

    float4 xa = *(const float4*)&x[(size_t)(m0 + xrow) * Cc + xkq * 4];
    float4 xb = *(const float4*)&x[(size_t)(m0 + xrow + 64) * Cc + xkq * 4];
    float4 wa, wb;
    if (tid < 128) {
        wa = *(const float4*)&W[(size_t)(2 * wkk) * Hh + wn];
        wb = *(const float4*)&W[(size_t)(2 * wkk + 1) * Hh + wn];
    }

    for (int c = 0; c < 64; c++) {
        Xh[xrow][2 * xkq + 0] = pack_hi(xa.x, xa.y);
        Xh[xrow][2 * xkq + 1] = pack_hi(xa.z, xa.w);
        Xl[xrow][2 * xkq + 0] = pack_rn(xa.x - trunc_bf(xa.x), xa.y - trunc_bf(xa.y));
        Xl[xrow][2 * xkq + 1] = pack_rn(xa.z - trunc_bf(xa.z), xa.w - trunc_bf(xa.w));
        Xh[xrow + 64][2 * xkq + 0] = pack_hi(xb.x, xb.y);
        Xh[xrow + 64][2 * xkq + 1] = pack_hi(xb.z, xb.w);
        Xl[xrow + 64][2 * xkq + 0] = pack_rn(xb.x - trunc_bf(xb.x), xb.y - trunc_bf(xb.y));
        Xl[xrow + 64][2 * xkq + 1] = pack_rn(xb.z - trunc_bf(xb.z), xb.w - trunc_bf(xb.w));
        if (tid < 128) {
            Wph[wkk][wn + 0] = pack_hi(wa.x, wb.x);
            Wph[wkk][wn + 1] = pack_hi(wa.y, wb.y);
            Wph[wkk][wn + 2] = pack_hi(wa.z, wb.z);
            Wph[wkk][wn + 3] = pack_hi(wa.w, wb.w);
            Wpl[wkk][wn + 0] = pack_rn(wa.x - trunc_bf(wa.x), wb.x - trunc_bf(wb.x));
            Wpl[wkk][wn + 1] = pack_rn(wa.y - trunc_bf(wa.y), wb.y - trunc_bf(wb.y));
            Wpl[wkk][wn + 2] = pack_rn(wa.z - trunc_bf(wa.z), wb.z - trunc_bf(wb.z));
            Wpl[wkk][wn + 3] = pack_rn(wa.w - trunc_bf(wa.w), wb.w - trunc_bf(wb.w));
        }
        __syncthreads();

        if (c < 63) {
            int k0 = (c + 1) * 16;
            xa = *(const float4*)&x[(size_t)(m0 + xrow) * Cc + k0 + xkq * 4];
            xb = *(const float4*)&x[(size_t)(m0 + xrow + 64) * Cc + k0 + xkq * 4];
            if (tid < 128) {
                wa = *(const float4*)&W[(size_t)(k0 + 2 * wkk) * Hh + wn];
                wb = *(const float4*)&W[(size_t)(k0 + 2 * wkk + 1) * Hh + wn];
            }
        }

        const int r0 = w * 16 + gid;
        unsigned a0h = Xh[r0][tig],     a1h = Xh[r0 + 8][tig];
        unsigned a2h = Xh[r0][tig + 4], a3h = Xh[r0 + 8][tig + 4];
        unsigned a0l = Xl[r0][tig],     a1l = Xl[r0 + 8][tig];
        unsigned a2l = Xl[r0][tig + 4], a3l = Xl[r0 + 8][tig + 4];

        #pragma unroll
        for (int jn = 0; jn < 8; jn++) {
            int n = gid + 8 * jn;
            unsigned bh0 = Wph[tig][n], bh1 = Wph[tig + 4][n];
            unsigned bl0 = Wpl[tig][n], bl1 = Wpl[tig + 4][n];
            mma16816(acc[jn], a0h, a1h, a2h, a3h, bh0, bh1);
            mma16816(acc[jn], a0l, a1l, a2l, a3l, bh0, bh1);
            mma16816(acc[jn], a0h, a1h, a2h, a3h, bl0, bl1);
        }
        __syncthreads();
    }

    const float sc = (which == 0) ? 0.03125f : 1.0f;   // fold softmax scale into q
    const int r0 = m0 + w * 16 + gid;
    #pragma unroll
    for (int jn = 0; jn < 8; jn++) {
        float c0 = acc[jn][0] * sc, c1 = acc[jn][1] * sc;
        float c2 = acc[jn][2] * sc, c3 = acc[jn][3] * sc;
        int p = 4 * jn + tig;
        OH[(size_t)r0 * 32 + p]       = pack_hi(c0, c1);
        OL[(size_t)r0 * 32 + p]       = pack_rn(c0 - trunc_bf(c0), c1 - trunc_bf(c1));
        OH[(size_t)(r0 + 8) * 32 + p] = pack_hi(c2, c3);
        OL[(size_t)(r0 + 8) * 32 + p] = pack_rn(c2 - trunc_bf(c2), c3 - trunc_bf(c3));
    }
}

// ---------------------------------------------------------------------------
// Kernel 2: causal flash attention with split-bf16 mma.
// CTA: 128 thr / 4 warps, Q tile 64 rows (16/warp), KV tile 64 tokens.
// K stored [token][h-pair] (native layout = B fragment, conflict-free reads).
// V stored [token-pair][h] via shfl-exchange repack.
// ---------------------------------------------------------------------------
#define PK 36   // K row stride (u32): reads bank = lane, conflict-free
#define PV 72   // V row stride (u32): reads 8*tig+gid, conflict-free

__global__ __launch_bounds__(128) void attn_kernel(float* __restrict__ o) {
    __shared__ unsigned sKh[64 * PK], sKl[64 * PK];
    __shared__ unsigned sVh[32 * PV], sVl[32 * PV];

    const int b   = blockIdx.y;
    const int bx  = blockIdx.x;
    // interleave heavy/light causal tiles: adjacent bx alternate long/short
    const int qi  = (bx & 1) ? (63 - (bx >> 1)) : (bx >> 1);
    const int q0  = qi * 64;
    const int tid = threadIdx.x;
    const int w   = tid >> 5;
    const int lane = tid & 31;
    const int gid = lane >> 2;
    const int tig = lane & 3;

    const unsigned* __restrict__ QH = g_qh + (size_t)b * Tt * 32;
    const unsigned* __restrict__ QL = g_ql + (size_t)b * Tt * 32;
    const unsigned* __restrict__ KH = g_kh + (size_t)b * Tt * 32;
    const unsigned* __restrict__ KL = g_kl + (size_t)b * Tt * 32;
    const unsigned* __restrict__ VH = g_vh + (size_t)b * Tt * 32;
    const unsigned* __restrict__ VL = g_vl + (size_t)b * Tt * 32;

    // Q fragments, register resident: [h-chunk 0..3][a0..a3]
    unsigned qh[4][4], ql[4][4];
    {
        const int r0 = q0 + w * 16 + gid;
        #pragma unroll
        for (int c = 0; c < 4; c++) {
            qh[c][0] = QH[(size_t)r0 * 32 + 8 * c + tig];
            qh[c][1] = QH[(size_t)(r0 + 8) * 32 + 8 * c + tig];
            qh[c][2] = QH[(size_t)r0 * 32 + 8 * c + tig + 4];
            qh[c][3] = QH[(size_t)(r0 + 8) * 32 + 8 * c + tig + 4];
            ql[c][0] = QL[(size_t)r0 * 32 + 8 * c + tig];
            ql[c][1] = QL[(size_t)(r0 + 8) * 32 + 8 * c + tig];
            ql[c][2] = QL[(size_t)r0 * 32 + 8 * c + tig + 4];
            ql[c][3] = QL[(size_t)(r0 + 8) * 32 + 8 * c + tig + 4];
        }
    }

    float o_acc[8][4];
    #pragma unroll
    for (int j = 0; j < 8; j++)
        #pragma unroll
        for (int e = 0; e < 4; e++) o_acc[j][e] = 0.f;
    float m0 = -1e30f, m1 = -1e30f;
    float l0 = 0.f, l1 = 0.f;

    // loader slot fields: 512 (t, h4) slots over 128 threads x 4
    int t_[4], h4_[4];
    #pragma unroll
    for (int i = 0; i < 4; i++) {
        int sl = tid + 128 * i;
        t_[i]  = (sl & 7) + 8 * ((sl >> 6) & 7);
        h4_[i] = (sl >> 3) & 7;
    }
    const unsigned odd = tid & 1;   // token parity (t_[i] & 1 == tid & 1)

    const int nkv = qi + 1;
    for (int kt = 0; kt < nkv; kt++) {
        const int k0 = kt * 64;

        __syncthreads();   // previous tile compute done before overwrite
        #pragma unroll
        for (int i = 0; i < 4; i++) {
            const int t = t_[i], h4 = h4_[i];
            uint4 kh = *(const uint4*)&KH[(size_t)(k0 + t) * 32 + 4 * h4];
            uint4 kl = *(const uint4*)&KL[(size_t)(k0 + t) * 32 + 4 * h4];
            uint4 vh = *(const uint4*)&VH[(size_t)(k0 + t) * 32 + 4 * h4];
            uint4 vl = *(const uint4*)&VL[(size_t)(k0 + t) * 32 + 4 * h4];

            // K: native [token][h-pair] layout IS the QK^T B fragment
            *(uint4*)&sKh[t * PK + 4 * h4] = kh;
            *(uint4*)&sKl[t * PK + 4 * h4] = kl;

            // V: token-pair repack via lane exchange (lanes tid, tid^1 hold t, t^1)
            const int tp = t >> 1;
            unsigned vv[4] = {vh.x, vh.y, vh.z, vh.w};
            unsigned ww[4] = {vl.x, vl.y, vl.z, vl.w};
            #pragma unroll
            for (int j = 0; j < 4; j++) {
                unsigned ph = __shfl_xor_sync(0xffffffffu, vv[j], 1);
                unsigned pl = __shfl_xor_sync(0xffffffffu, ww[j], 1);
                int h = 8 * h4 + 2 * j + odd;
                unsigned rh = odd ? ((ph >> 16) | (vv[j] & 0xFFFF0000u))
                                  : ((vv[j] & 0xFFFFu) | (ph << 16));
                unsigned rl = odd ? ((pl >> 16) | (ww[j] & 0xFFFF0000u))
                                  : ((ww[j] & 0xFFFFu) | (pl << 16));
                sVh[tp * PV + h] = rh;
                sVl[tp * PV + h] = rl;
            }
        }
        __syncthreads();

        // ---- S = Q K^T (scale already folded into q) ----
        float s[8][4];
        #pragma unroll
        for (int jn = 0; jn < 8; jn++) {
            s[jn][0] = s[jn][1] = s[jn][2] = s[jn][3] = 0.f;
            int n = gid + 8 * jn;
            #pragma unroll
            for (int c = 0; c < 4; c++) {
                unsigned bh0 = sKh[n * PK + 8 * c + tig];
                unsigned bh1 = sKh[n * PK + 8 * c + tig + 4];
                unsigned bl0 = sKl[n * PK + 8 * c + tig];
                unsigned bl1 = sKl[n * PK + 8 * c + tig + 4];
                mma16816(s[jn], qh[c][0], qh[c][1], qh[c][2], qh[c][3], bh0, bh1);
                mma16816(s[jn], ql[c][0], ql[c][1], ql[c][2], ql[c][3], bh0, bh1);
                mma16816(s[jn], qh[c][0], qh[c][1], qh[c][2], qh[c][3], bl0, bl1);
            }
        }

        // ---- causal mask (only the diagonal tile can exceed) ----
        if (kt == qi) {
            const int r0g = q0 + w * 16 + gid, r1g = r0g + 8;
            #pragma unroll
            for (int jn = 0; jn < 8; jn++) {
                int col = k0 + 8 * jn + 2 * tig;
                if (col     > r0g) s[jn][0] = -1e30f;
                if (col + 1 > r0g) s[jn][1] = -1e30f;
                if (col     > r1g) s[jn][2] = -1e30f;
                if (col + 1 > r1g) s[jn][3] = -1e30f;
            }
        }

        // ---- online softmax (rows gid, gid+8; quad = lanes sharing gid) ----
        float tm0 = -1e30f, tm1 = -1e30f;
        #pragma unroll
        for (int jn = 0; jn < 8; jn++) {
            tm0 = fmaxf(tm0, fmaxf(s[jn][0], s[jn][1]));
            tm1 = fmaxf(tm1, fmaxf(s[jn][2], s[jn][3]));
        }
        tm0 = fmaxf(tm0, __shfl_xor_sync(0xffffffffu, tm0, 1));
        tm0 = fmaxf(tm0, __shfl_xor_sync(0xffffffffu, tm0, 2));
        tm1 = fmaxf(tm1, __shfl_xor_sync(0xffffffffu, tm1, 1));
        tm1 = fmaxf(tm1, __shfl_xor_sync(0xffffffffu, tm1, 2));

        float mn0 = fmaxf(m0, tm0), mn1 = fmaxf(m1, tm1);
        float al0 = __expf(m0 - mn0), al1 = __expf(m1 - mn1);
        m0 = mn0; m1 = mn1;

        float rs0 = 0.f, rs1 = 0.f;
        #pragma unroll
        for (int jn = 0; jn < 8; jn++) {
            s[jn][0] = __expf(s[jn][0] - mn0);
            s[jn][1] = __expf(s[jn][1] - mn0);
            s[jn][2] = __expf(s[jn][2] - mn1);
            s[jn][3] = __expf(s[jn][3] - mn1);
            rs0 += s[jn][0] + s[jn][1];
            rs1 += s[jn][2] + s[jn][3];
        }
        l0 = l0 * al0 + rs0;
        l1 = l1 * al1 + rs1;
        #pragma unroll
        for (int jn = 0; jn < 8; jn++) {
            o_acc[jn][0] *= al0; o_acc[jn][1] *= al0;
            o_acc[jn][2] *= al1; o_acc[jn][3] *= al1;
        }

        // ---- O += P V (P fragments rebuilt from S registers) ----
        #pragma unroll
        for (int jp = 0; jp < 4; jp++) {
            unsigned p0h = pack_hi(s[2 * jp][0], s[2 * jp][1]);
            unsigned p1h = pack_hi(s[2 * jp][2], s[2 * jp][3]);
            unsigned p2h = pack_hi(s[2 * jp + 1][0], s[2 * jp + 1][1]);
            unsigned p3h = pack_hi(s[2 * jp + 1][2], s[2 * jp + 1][3]);
            unsigned p0l = pack_rn(s[2 * jp][0] - trunc_bf(s[2 * jp][0]),
                                   s[2 * jp][1] - trunc_bf(s[2 * jp][1]));
            unsigned p1l = pack_rn(s[2 * jp][2] - trunc_bf(s[2 * jp][2]),
                                   s[2 * jp][3] - trunc_bf(s[2 * jp][3]));
            unsigned p2l = pack_rn(s[2 * jp + 1][0] - trunc_bf(s[2 * jp + 1][0]),
                                   s[2 * jp + 1][1] - trunc_bf(s[2 * jp + 1][1]));
            unsigned p3l = pack_rn(s[2 * jp + 1][2] - trunc_bf(s[2 * jp + 1][2]),
                                   s[2 * jp + 1][3] - trunc_bf(s[2 * jp + 1][3]));
            #pragma unroll
            for (int jn = 0; jn < 8; jn++) {
                int n = gid + 8 * jn;
                unsigned bh0 = sVh[(8 * jp + tig) * PV + n];
                unsigned bh1 = sVh[(8 * jp + tig + 4) * PV + n];
                unsigned bl0 = sVl[(8 * jp + tig) * PV + n];
                unsigned bl1 = sVl[(8 * jp + tig + 4) * PV + n];
                mma16816(o_acc[jn], p0h, p1h, p2h, p3h, bh0, bh1);
                mma16816(o_acc[jn], p0l, p1l, p2l, p3l, bh0, bh1);
                mma16816(o_acc[jn], p0h, p1h, p2h, p3h, bl0, bl1);
            }
        }
    }

    // ---- epilogue: reduce l across quad, normalize, store ----
    l0 += __shfl_xor_sync(0xffffffffu, l0, 1);
    l0 += __shfl_xor_sync(0xffffffffu, l0, 2);
    l1 += __shfl_xor_sync(0xffffffffu, l1, 1);
    l1 += __shfl_xor_sync(0xffffffffu, l1, 2);
    float inv0 = 1.0f / l0, inv1 = 1.0f / l1;

    const size_t r0 = (size_t)b * Tt + q0 + w * 16 + gid;
    #pragma unroll
    for (int jn = 0; jn < 8; jn++) {
        int n = 8 * jn + 2 * tig;
        *(float2*)&o[r0 * 64 + n] =
            make_float2(o_acc[jn][0] * inv0, o_acc[jn][1] * inv0);
        *(float2*)&o[(r0 + 8) * 64 + n] =
            make_float2(o_acc[jn][2] * inv1, o_acc[jn][3] * inv1);
    }
}

// ---------------------------------------------------------------------------
extern "C" void kernel_launch(void* const* d_in, const int* in_sizes, int n_in,
                              void* d_out, int out_size) {
    const float* x  = (const float*)d_in[0];
    const float* Wq = (const float*)d_in[1];
    const float* Wk = (const float*)d_in[2];
    const float* Wv = (const float*)d_in[3];
    float* out = (float*)d_out;

    qkv_gemm<<<dim3(BT / 128, 3), 256>>>(x, Wq, Wk, Wv);
    attn_kernel<<<dim3(64, Bsz), 128>>>(out);
}

// round 7
// speedup vs baseline: 1.8583x; 1.8583x over previous
#include <cuda_runtime.h>
#include <math.h>

#define Bsz 4
#define Tt  4096
#define Cc  1024
#define Hh  64
#define BT  (Bsz*Tt)

// q,k: [token][32] u32 (bf16x2 over h-pairs).  v: token-paired [t/2][64 h] u32
// (u16 lo = even token, u16 hi = odd token).  q pre-scaled by C^-0.5 = 1/32.
__device__ unsigned g_qh[BT*32];
__device__ unsigned g_ql[BT*32];
__device__ unsigned g_kh[BT*32];
__device__ unsigned g_kl[BT*32];
__device__ unsigned g_vh[BT*32];
__device__ unsigned g_vl[BT*32];

// split-KV partials
__device__ float g_op[2][BT*64];
__device__ float g_m[2][BT];
__device__ float g_l[2][BT];

// ---------------------------------------------------------------------------
// helpers
// ---------------------------------------------------------------------------
__device__ __forceinline__ void mma16816(float c[4], unsigned a0, unsigned a1,
                                         unsigned a2, unsigned a3,
                                         unsigned b0, unsigned b1) {
    asm volatile(
        "mma.sync.aligned.m16n8k16.row.col.f32.bf16.bf16.f32 "
        "{%0,%1,%2,%3}, {%4,%5,%6,%7}, {%8,%9}, {%0,%1,%2,%3};\n"
        : "+f"(c[0]), "+f"(c[1]), "+f"(c[2]), "+f"(c[3])
        : "r"(a0), "r"(a1), "r"(a2), "r"(a3), "r"(b0), "r"(b1));
}
__device__ __forceinline__ unsigned pack_hi(float x, float y) {
    return (__float_as_uint(x) >> 16) | (__float_as_uint(y) & 0xFFFF0000u);
}
__device__ __forceinline__ float trunc_bf(float x) {
    return __uint_as_float(__float_as_uint(x) & 0xFFFF0000u);
}
__device__ __forceinline__ unsigned pack_rn(float x, float y) {
    unsigned r;
    asm("cvt.rn.bf16x2.f32 %0, %1, %2;" : "=r"(r) : "f"(y), "f"(x));
    return r;
}
__device__ __forceinline__ void cpa16(unsigned dst, const void* src) {
    asm volatile("cp.async.cg.shared.global [%0], [%1], 16;\n"
                 :: "r"(dst), "l"(src));
}
#define CP_COMMIT() asm volatile("cp.async.commit_group;\n" ::: "memory")
#define CP_WAIT(n)  asm volatile("cp.async.wait_group %0;\n" :: "n"(n) : "memory")

// ---------------------------------------------------------------------------
// Kernel 1: QKV projection -> split-bf16 pairs.  (V in token-paired layout)
// ---------------------------------------------------------------------------
__global__ __launch_bounds__(256) void qkv_gemm(const float* __restrict__ x,
                                                const float* __restrict__ Wq,
                                                const float* __restrict__ Wk,
                                                const float* __restrict__ Wv) {
    __shared__ unsigned Xh[128][12], Xl[128][12];
    __shared__ unsigned Wph[8][72], Wpl[8][72];

    const int which = blockIdx.y;
    const float* __restrict__ W = (which == 0) ? Wq : (which == 1) ? Wk : Wv;
    unsigned* __restrict__ OH = (which == 0) ? g_qh : (which == 1) ? g_kh : g_vh;
    unsigned* __restrict__ OL = (which == 0) ? g_ql : (which == 1) ? g_kl : g_vl;

    const int m0   = blockIdx.x * 128;
    const int tid  = threadIdx.x;
    const int w    = tid >> 5;
    const int lane = tid & 31;
    const int gid  = lane >> 2;
    const int tig  = lane & 3;

    const int xrow = tid >> 2;
    const int xkq  = tid & 3;
    const int wkk  = tid >> 4;
    const int wn   = (tid & 15) * 4;

    float acc[8][4];
    #pragma unroll
    for (int j = 0; j < 8; j++)
        #pragma unroll
        for (int e = 0; e < 4; e++) acc[j][e] = 0.f;

    float4 xa = *(const float4*)&x[(size_t)(m0 + xrow) * Cc + xkq * 4];
    float4 xb = *(const float4*)&x[(size_t)(m0 + xrow + 64) * Cc + xkq * 4];
    float4 wa, wb;
    if (tid < 128) {
        wa = *(const float4*)&W[(size_t)(2 * wkk) * Hh + wn];
        wb = *(const float4*)&W[(size_t)(2 * wkk + 1) * Hh + wn];
    }

    for (int c = 0; c < 64; c++) {
        Xh[xrow][2 * xkq + 0] = pack_hi(xa.x, xa.y);
        Xh[xrow][2 * xkq + 1] = pack_hi(xa.z, xa.w);
        Xl[xrow][2 * xkq + 0] = pack_rn(xa.x - trunc_bf(xa.x), xa.y - trunc_bf(xa.y));
        Xl[xrow][2 * xkq + 1] = pack_rn(xa.z - trunc_bf(xa.z), xa.w - trunc_bf(xa.w));
        Xh[xrow + 64][2 * xkq + 0] = pack_hi(xb.x, xb.y);
        Xh[xrow + 64][2 * xkq + 1] = pack_hi(xb.z, xb.w);
        Xl[xrow + 64][2 * xkq + 0] = pack_rn(xb.x - trunc_bf(xb.x), xb.y - trunc_bf(xb.y));
        Xl[xrow + 64][2 * xkq + 1] = pack_rn(xb.z - trunc_bf(xb.z), xb.w - trunc_bf(xb.w));
        if (tid < 128) {
            Wph[wkk][wn + 0] = pack_hi(wa.x, wb.x);
            Wph[wkk][wn + 1] = pack_hi(wa.y, wb.y);
            Wph[wkk][wn + 2] = pack_hi(wa.z, wb.z);
            Wph[wkk][wn + 3] = pack_hi(wa.w, wb.w);
            Wpl[wkk][wn + 0] = pack_rn(wa.x - trunc_bf(wa.x), wb.x - trunc_bf(wb.x));
            Wpl[wkk][wn + 1] = pack_rn(wa.y - trunc_bf(wa.y), wb.y - trunc_bf(wb.y));
            Wpl[wkk][wn + 2] = pack_rn(wa.z - trunc_bf(wa.z), wb.z - trunc_bf(wb.z));
            Wpl[wkk][wn + 3] = pack_rn(wa.w - trunc_bf(wa.w), wb.w - trunc_bf(wb.w));
        }
        __syncthreads();

        if (c < 63) {
            int k0 = (c + 1) * 16;
            xa = *(const float4*)&x[(size_t)(m0 + xrow) * Cc + k0 + xkq * 4];
            xb = *(const float4*)&x[(size_t)(m0 + xrow + 64) * Cc + k0 + xkq * 4];
            if (tid < 128) {
                wa = *(const float4*)&W[(size_t)(k0 + 2 * wkk) * Hh + wn];
                wb = *(const float4*)&W[(size_t)(k0 + 2 * wkk + 1) * Hh + wn];
            }
        }

        const int r = w * 16 + gid;
        unsigned a0h = Xh[r][tig],     a1h = Xh[r + 8][tig];
        unsigned a2h = Xh[r][tig + 4], a3h = Xh[r + 8][tig + 4];
        unsigned a0l = Xl[r][tig],     a1l = Xl[r + 8][tig];
        unsigned a2l = Xl[r][tig + 4], a3l = Xl[r + 8][tig + 4];

        #pragma unroll
        for (int jn = 0; jn < 8; jn++) {
            int n = gid + 8 * jn;
            unsigned bh0 = Wph[tig][n], bh1 = Wph[tig + 4][n];
            unsigned bl0 = Wpl[tig][n], bl1 = Wpl[tig + 4][n];
            mma16816(acc[jn], a0h, a1h, a2h, a3h, bh0, bh1);
            mma16816(acc[jn], a0l, a1l, a2l, a3l, bh0, bh1);
            mma16816(acc[jn], a0h, a1h, a2h, a3h, bl0, bl1);
        }
        __syncthreads();
    }

    const int r0 = m0 + w * 16 + gid;
    if (which < 2) {
        const float sc = (which == 0) ? 0.03125f : 1.0f;
        #pragma unroll
        for (int jn = 0; jn < 8; jn++) {
            float c0 = acc[jn][0] * sc, c1 = acc[jn][1] * sc;
            float c2 = acc[jn][2] * sc, c3 = acc[jn][3] * sc;
            int p = 4 * jn + tig;
            OH[(size_t)r0 * 32 + p]       = pack_hi(c0, c1);
            OL[(size_t)r0 * 32 + p]       = pack_rn(c0 - trunc_bf(c0), c1 - trunc_bf(c1));
            OH[(size_t)(r0 + 8) * 32 + p] = pack_hi(c2, c3);
            OL[(size_t)(r0 + 8) * 32 + p] = pack_rn(c2 - trunc_bf(c2), c3 - trunc_bf(c3));
        }
    } else {
        // V: token-paired layout.  lanes (gid, gid^1) = adjacent token rows.
        #pragma unroll
        for (int jn = 0; jn < 8; jn++) {
            float c0 = acc[jn][0], c1 = acc[jn][1];
            float c2 = acc[jn][2], c3 = acc[jn][3];
            float d0 = __shfl_xor_sync(0xffffffffu, c0, 4);
            float d1 = __shfl_xor_sync(0xffffffffu, c1, 4);
            float d2 = __shfl_xor_sync(0xffffffffu, c2, 4);
            float d3 = __shfl_xor_sync(0xffffffffu, c3, 4);
            int p = 4 * jn + tig;
            size_t tp0 = (size_t)(r0 >> 1) * 64;
            size_t tp1 = (size_t)((r0 + 8) >> 1) * 64;
            if (!(gid & 1)) {       // even token row: write h = 2p
                OH[tp0 + 2 * p] = pack_hi(c0, d0);
                OL[tp0 + 2 * p] = pack_rn(c0 - trunc_bf(c0), d0 - trunc_bf(d0));
                OH[tp1 + 2 * p] = pack_hi(c2, d2);
                OL[tp1 + 2 * p] = pack_rn(c2 - trunc_bf(c2), d2 - trunc_bf(d2));
            } else {                // odd token row: write h = 2p+1
                OH[tp0 + 2 * p + 1] = pack_hi(d1, c1);
                OL[tp0 + 2 * p + 1] = pack_rn(d1 - trunc_bf(d1), c1 - trunc_bf(c1));
                OH[tp1 + 2 * p + 1] = pack_hi(d3, c3);
                OL[tp1 + 2 * p + 1] = pack_rn(d3 - trunc_bf(d3), c3 - trunc_bf(c3));
            }
        }
    }
}

// ---------------------------------------------------------------------------
// Kernel 2: causal flash attention, split-KV 2-way, cp.async double-buffered.
// CTA: 128 thr / 4 warps, Q tile 64 rows, KV tile 64 tokens.
// ---------------------------------------------------------------------------
#define PK 36
#define PV 72
// per-stage u32 offsets: KH 0, KL 2304, VH 4608, VL 6912; stage = 9216 u32
#define STG_U32 9216
#define ATTN_SMEM (2 * STG_U32 * 4)   // 73728 B

__global__ __launch_bounds__(128) void attn_kernel() {
    extern __shared__ unsigned smem[];

    const int b   = blockIdx.y;
    const int bx  = blockIdx.x;
    const int s   = bx & 1;
    const int qih = bx >> 1;
    const int qi  = (qih & 1) ? (63 - (qih >> 1)) : (qih >> 1);
    const int q0  = qi * 64;
    const int tid = threadIdx.x;
    const int w   = tid >> 5;
    const int lane = tid & 31;
    const int gid = lane >> 2;
    const int tig = lane & 3;

    // kv tile range for this split
    const int half = (qi + 1) >> 1;
    const int kv0 = s ? half : 0;
    const int kv1 = s ? (qi + 1) : half;
    const int nt  = kv1 - kv0;

    float* __restrict__ op = g_op[s] + ((size_t)b * Tt + q0) * 64;

    if (nt == 0) {   // empty split: zero partial
        for (int i = tid; i < 64 * 64; i += 128) op[i] = 0.f;
        if (tid < 64) {
            g_m[s][(size_t)b * Tt + q0 + tid] = -1e30f;
            g_l[s][(size_t)b * Tt + q0 + tid] = 0.f;
        }
        return;
    }

    const unsigned* __restrict__ QH = g_qh + (size_t)b * Tt * 32;
    const unsigned* __restrict__ QL = g_ql + (size_t)b * Tt * 32;
    const unsigned* __restrict__ KH = g_kh + (size_t)b * Tt * 32;
    const unsigned* __restrict__ KL = g_kl + (size_t)b * Tt * 32;
    const unsigned* __restrict__ VH = g_vh + (size_t)b * (Tt / 2) * 64;
    const unsigned* __restrict__ VL = g_vl + (size_t)b * (Tt / 2) * 64;

    const unsigned smbase = (unsigned)__cvta_generic_to_shared(smem);

    // cp.async slot fields
    const int kr = tid >> 3, kc = tid & 7;      // +8 rows per i
    const int vr = tid >> 4, vc = tid & 15;     // +4 rows per i

    // prefetch helper (macro to keep addresses in registers)
    #define PREFETCH(j) do {                                                    \
        const int kt__ = kv0 + (j);                                             \
        const unsigned bs__ = smbase + ((j) & 1) * (STG_U32 * 4);               \
        const int k0__ = kt__ * 64, kp__ = kt__ * 32;                           \
        _Pragma("unroll")                                                       \
        for (int i = 0; i < 4; i++) {                                           \
            int krr = kr + 16 * i;                                              \
            cpa16(bs__ + krr * 144 + kc * 16,          KH + (size_t)(k0__ + krr) * 32 + 4 * kc); \
            cpa16(bs__ + 9216 + krr * 144 + kc * 16,   KL + (size_t)(k0__ + krr) * 32 + 4 * kc); \
            int vrr = vr + 8 * i;                                               \
            cpa16(bs__ + 18432 + vrr * 288 + vc * 16,  VH + (size_t)(kp__ + vrr) * 64 + 4 * vc); \
            cpa16(bs__ + 27648 + vrr * 288 + vc * 16,  VL + (size_t)(kp__ + vrr) * 64 + 4 * vc); \
        }                                                                       \
        CP_COMMIT();                                                            \
    } while (0)

    // Q fragments, register resident
    unsigned qh[4][4], ql[4][4];
    {
        const int r0 = q0 + w * 16 + gid;
        #pragma unroll
        for (int c = 0; c < 4; c++) {
            qh[c][0] = QH[(size_t)r0 * 32 + 8 * c + tig];
            qh[c][1] = QH[(size_t)(r0 + 8) * 32 + 8 * c + tig];
            qh[c][2] = QH[(size_t)r0 * 32 + 8 * c + tig + 4];
            qh[c][3] = QH[(size_t)(r0 + 8) * 32 + 8 * c + tig + 4];
            ql[c][0] = QL[(size_t)r0 * 32 + 8 * c + tig];
            ql[c][1] = QL[(size_t)(r0 + 8) * 32 + 8 * c + tig];
            ql[c][2] = QL[(size_t)r0 * 32 + 8 * c + tig + 4];
            ql[c][3] = QL[(size_t)(r0 + 8) * 32 + 8 * c + tig + 4];
        }
    }

    PREFETCH(0);

    float o_acc[8][4];
    #pragma unroll
    for (int j = 0; j < 8; j++)
        #pragma unroll
        for (int e = 0; e < 4; e++) o_acc[j][e] = 0.f;
    float m0 = -1e30f, m1 = -1e30f;
    float l0 = 0.f, l1 = 0.f;

    for (int j = 0; j < nt; j++) {
        const int kt = kv0 + j;
        const int k0 = kt * 64;

        if (j + 1 < nt) { PREFETCH(j + 1); CP_WAIT(1); }
        else            { CP_WAIT(0); }
        __syncthreads();

        const unsigned* sKh = smem + (j & 1) * STG_U32;
        const unsigned* sKl = sKh + 2304;
        const unsigned* sVh = sKh + 4608;
        const unsigned* sVl = sKh + 6912;

        // ---- S = Q K^T ----
        float sv[8][4];
        #pragma unroll
        for (int jn = 0; jn < 8; jn++) {
            sv[jn][0] = sv[jn][1] = sv[jn][2] = sv[jn][3] = 0.f;
            int n = gid + 8 * jn;
            #pragma unroll
            for (int c = 0; c < 4; c++) {
                unsigned bh0 = sKh[n * PK + 8 * c + tig];
                unsigned bh1 = sKh[n * PK + 8 * c + tig + 4];
                unsigned bl0 = sKl[n * PK + 8 * c + tig];
                unsigned bl1 = sKl[n * PK + 8 * c + tig + 4];
                mma16816(sv[jn], qh[c][0], qh[c][1], qh[c][2], qh[c][3], bh0, bh1);
                mma16816(sv[jn], ql[c][0], ql[c][1], ql[c][2], ql[c][3], bh0, bh1);
                mma16816(sv[jn], qh[c][0], qh[c][1], qh[c][2], qh[c][3], bl0, bl1);
            }
        }

        // ---- causal mask (diagonal tile only; only in split 1) ----
        if (kt == qi) {
            const int r0g = q0 + w * 16 + gid, r1g = r0g + 8;
            #pragma unroll
            for (int jn = 0; jn < 8; jn++) {
                int col = k0 + 8 * jn + 2 * tig;
                if (col     > r0g) sv[jn][0] = -1e30f;
                if (col + 1 > r0g) sv[jn][1] = -1e30f;
                if (col     > r1g) sv[jn][2] = -1e30f;
                if (col + 1 > r1g) sv[jn][3] = -1e30f;
            }
        }

        // ---- online softmax ----
        float tm0 = -1e30f, tm1 = -1e30f;
        #pragma unroll
        for (int jn = 0; jn < 8; jn++) {
            tm0 = fmaxf(tm0, fmaxf(sv[jn][0], sv[jn][1]));
            tm1 = fmaxf(tm1, fmaxf(sv[jn][2], sv[jn][3]));
        }
        tm0 = fmaxf(tm0, __shfl_xor_sync(0xffffffffu, tm0, 1));
        tm0 = fmaxf(tm0, __shfl_xor_sync(0xffffffffu, tm0, 2));
        tm1 = fmaxf(tm1, __shfl_xor_sync(0xffffffffu, tm1, 1));
        tm1 = fmaxf(tm1, __shfl_xor_sync(0xffffffffu, tm1, 2));

        float mn0 = fmaxf(m0, tm0), mn1 = fmaxf(m1, tm1);
        float al0 = __expf(m0 - mn0), al1 = __expf(m1 - mn1);
        m0 = mn0; m1 = mn1;

        float rs0 = 0.f, rs1 = 0.f;
        #pragma unroll
        for (int jn = 0; jn < 8; jn++) {
            sv[jn][0] = __expf(sv[jn][0] - mn0);
            sv[jn][1] = __expf(sv[jn][1] - mn0);
            sv[jn][2] = __expf(sv[jn][2] - mn1);
            sv[jn][3] = __expf(sv[jn][3] - mn1);
            rs0 += sv[jn][0] + sv[jn][1];
            rs1 += sv[jn][2] + sv[jn][3];
        }
        l0 = l0 * al0 + rs0;
        l1 = l1 * al1 + rs1;
        #pragma unroll
        for (int jn = 0; jn < 8; jn++) {
            o_acc[jn][0] *= al0; o_acc[jn][1] *= al0;
            o_acc[jn][2] *= al1; o_acc[jn][3] *= al1;
        }

        // ---- O += P V ----
        #pragma unroll
        for (int jp = 0; jp < 4; jp++) {
            unsigned p0h = pack_hi(sv[2 * jp][0], sv[2 * jp][1]);
            unsigned p1h = pack_hi(sv[2 * jp][2], sv[2 * jp][3]);
            unsigned p2h = pack_hi(sv[2 * jp + 1][0], sv[2 * jp + 1][1]);
            unsigned p3h = pack_hi(sv[2 * jp + 1][2], sv[2 * jp + 1][3]);
            unsigned p0l = pack_rn(sv[2 * jp][0] - trunc_bf(sv[2 * jp][0]),
                                   sv[2 * jp][1] - trunc_bf(sv[2 * jp][1]));
            unsigned p1l = pack_rn(sv[2 * jp][2] - trunc_bf(sv[2 * jp][2]),
                                   sv[2 * jp][3] - trunc_bf(sv[2 * jp][3]));
            unsigned p2l = pack_rn(sv[2 * jp + 1][0] - trunc_bf(sv[2 * jp + 1][0]),
                                   sv[2 * jp + 1][1] - trunc_bf(sv[2 * jp + 1][1]));
            unsigned p3l = pack_rn(sv[2 * jp + 1][2] - trunc_bf(sv[2 * jp + 1][2]),
                                   sv[2 * jp + 1][3] - trunc_bf(sv[2 * jp + 1][3]));
            #pragma unroll
            for (int jn = 0; jn < 8; jn++) {
                int n = gid + 8 * jn;
                unsigned bh0 = sVh[(8 * jp + tig) * PV + n];
                unsigned bh1 = sVh[(8 * jp + tig + 4) * PV + n];
                unsigned bl0 = sVl[(8 * jp + tig) * PV + n];
                unsigned bl1 = sVl[(8 * jp + tig + 4) * PV + n];
                mma16816(o_acc[jn], p0h, p1h, p2h, p3h, bh0, bh1);
                mma16816(o_acc[jn], p0l, p1l, p2l, p3l, bh0, bh1);
                mma16816(o_acc[jn], p0h, p1h, p2h, p3h, bl0, bl1);
            }
        }
        __syncthreads();   // all warps done with stage (j&1) before overwrite
    }

    // ---- epilogue: write unnormalized partials + (m, l) ----
    l0 += __shfl_xor_sync(0xffffffffu, l0, 1);
    l0 += __shfl_xor_sync(0xffffffffu, l0, 2);
    l1 += __shfl_xor_sync(0xffffffffu, l1, 1);
    l1 += __shfl_xor_sync(0xffffffffu, l1, 2);

    const int rloc = w * 16 + gid;
    if (tig == 0) {
        g_m[s][(size_t)b * Tt + q0 + rloc]     = m0;
        g_l[s][(size_t)b * Tt + q0 + rloc]     = l0;
        g_m[s][(size_t)b * Tt + q0 + rloc + 8] = m1;
        g_l[s][(size_t)b * Tt + q0 + rloc + 8] = l1;
    }
    #pragma unroll
    for (int jn = 0; jn < 8; jn++) {
        int n = 8 * jn + 2 * tig;
        *(float2*)&op[(size_t)rloc * 64 + n]       = make_float2(o_acc[jn][0], o_acc[jn][1]);
        *(float2*)&op[(size_t)(rloc + 8) * 64 + n] = make_float2(o_acc[jn][2], o_acc[jn][3]);
    }
}

// ---------------------------------------------------------------------------
// Kernel 3: combine the two KV splits.
// ---------------------------------------------------------------------------
__global__ __launch_bounds__(256) void combine_kernel(float* __restrict__ o) {
    int idx = blockIdx.x * 256 + threadIdx.x;   // over BT*64
    int row = idx >> 6;
    float m0 = g_m[0][row], m1 = g_m[1][row];
    float l0 = g_l[0][row], l1 = g_l[1][row];
    float mx = fmaxf(m0, m1);
    float w0 = __expf(m0 - mx), w1 = __expf(m1 - mx);
    float inv = 1.0f / (w0 * l0 + w1 * l1);
    o[idx] = (w0 * g_op[0][idx] + w1 * g_op[1][idx]) * inv;
}

// ---------------------------------------------------------------------------
extern "C" void kernel_launch(void* const* d_in, const int* in_sizes, int n_in,
                              void* d_out, int out_size) {
    const float* x  = (const float*)d_in[0];
    const float* Wq = (const float*)d_in[1];
    const float* Wk = (const float*)d_in[2];
    const float* Wv = (const float*)d_in[3];
    float* out = (float*)d_out;

    qkv_gemm<<<dim3(BT / 128, 3), 256>>>(x, Wq, Wk, Wv);

    cudaFuncSetAttribute(attn_kernel,
                         cudaFuncAttributeMaxDynamicSharedMemorySize, ATTN_SMEM);
    attn_kernel<<<dim3(128, Bsz), 128, ATTN_SMEM>>>();

    combine_kernel<<<BT * 64 / 256, 256>>>(out);
}

// round 8
// speedup vs baseline: 2.0130x; 1.0833x over previous
#include <cuda_runtime.h>
#include <math.h>

#define Bsz 4
#define Tt  4096
#define Cc  1024
#define Hh  64
#define BT  (Bsz*Tt)

// q,k: [token][32] u32 (bf16x2 over h-pairs).  v: token-paired [t/2][64 h] u32
// (u16 lo = even token, u16 hi = odd token).  q pre-scaled by C^-0.5 = 1/32.
__device__ unsigned g_qh[BT*32];
__device__ unsigned g_ql[BT*32];
__device__ unsigned g_kh[BT*32];
__device__ unsigned g_kl[BT*32];
__device__ unsigned g_vh[BT*32];
__device__ unsigned g_vl[BT*32];

// split-KV partials
__device__ float g_op[2][BT*64];
__device__ float g_m[2][BT];
__device__ float g_l[2][BT];

// ---------------------------------------------------------------------------
// helpers
// ---------------------------------------------------------------------------
__device__ __forceinline__ void mma16816(float c[4], unsigned a0, unsigned a1,
                                         unsigned a2, unsigned a3,
                                         unsigned b0, unsigned b1) {
    asm volatile(
        "mma.sync.aligned.m16n8k16.row.col.f32.bf16.bf16.f32 "
        "{%0,%1,%2,%3}, {%4,%5,%6,%7}, {%8,%9}, {%0,%1,%2,%3};\n"
        : "+f"(c[0]), "+f"(c[1]), "+f"(c[2]), "+f"(c[3])
        : "r"(a0), "r"(a1), "r"(a2), "r"(a3), "r"(b0), "r"(b1));
}
__device__ __forceinline__ unsigned pack_hi(float x, float y) {
    return (__float_as_uint(x) >> 16) | (__float_as_uint(y) & 0xFFFF0000u);
}
__device__ __forceinline__ float trunc_bf(float x) {
    return __uint_as_float(__float_as_uint(x) & 0xFFFF0000u);
}
__device__ __forceinline__ unsigned pack_rn(float x, float y) {
    unsigned r;
    asm("cvt.rn.bf16x2.f32 %0, %1, %2;" : "=r"(r) : "f"(y), "f"(x));
    return r;
}
__device__ __forceinline__ void cpa16(unsigned dst, const void* src) {
    asm volatile("cp.async.cg.shared.global [%0], [%1], 16;\n"
                 :: "r"(dst), "l"(src));
}
#define CP_COMMIT() asm volatile("cp.async.commit_group;\n" ::: "memory")
#define CP_WAIT(n)  asm volatile("cp.async.wait_group %0;\n" :: "n"(n) : "memory")

// ---------------------------------------------------------------------------
// Kernel 1: FUSED QKV projection.  x loaded & packed ONCE, 3 B-matrices.
// CTA: 128 thr / 4 warps, tile M=64, N=64, K-chunk 16.
// Split-bf16: acc = Ah*Bh + Al*Bh + Ah*Bl.
// ---------------------------------------------------------------------------
__global__ __launch_bounds__(128) void qkv_gemm(const float* __restrict__ x,
                                                const float* __restrict__ Wq,
                                                const float* __restrict__ Wk,
                                                const float* __restrict__ Wv) {
    __shared__ unsigned Xh[64][12], Xl[64][12];        // [row][k-pair 0..7]
    __shared__ unsigned Wph[3][8][72], Wpl[3][8][72];  // [which][k-pair][n]

    const int m0   = blockIdx.x * 64;
    const int tid  = threadIdx.x;
    const int w    = tid >> 5;
    const int lane = tid & 31;
    const int gid  = lane >> 2;
    const int tig  = lane & 3;

    const int xrow = tid >> 1;            // 0..63
    const int xkq  = (tid & 1) << 1;      // float4 group 0 or 2 (8 floats/thread)
    const int wkk  = tid >> 4;            // k-pair 0..7
    const int wn   = (tid & 15) * 4;      // n 0..60

    const float* __restrict__ Ws[3] = {Wq, Wk, Wv};

    float acc[3][8][4];
    #pragma unroll
    for (int q = 0; q < 3; q++)
        #pragma unroll
        for (int j = 0; j < 8; j++)
            #pragma unroll
            for (int e = 0; e < 4; e++) acc[q][j][e] = 0.f;

    // prefetch chunk 0
    float4 xa = *(const float4*)&x[(size_t)(m0 + xrow) * Cc + xkq * 4];
    float4 xb = *(const float4*)&x[(size_t)(m0 + xrow) * Cc + (xkq + 1) * 4];
    float4 wva[3], wvb[3];
    #pragma unroll
    for (int q = 0; q < 3; q++) {
        wva[q] = *(const float4*)&Ws[q][(size_t)(2 * wkk) * Hh + wn];
        wvb[q] = *(const float4*)&Ws[q][(size_t)(2 * wkk + 1) * Hh + wn];
    }

    for (int c = 0; c < 64; c++) {
        Xh[xrow][2 * xkq + 0] = pack_hi(xa.x, xa.y);
        Xh[xrow][2 * xkq + 1] = pack_hi(xa.z, xa.w);
        Xl[xrow][2 * xkq + 0] = pack_rn(xa.x - trunc_bf(xa.x), xa.y - trunc_bf(xa.y));
        Xl[xrow][2 * xkq + 1] = pack_rn(xa.z - trunc_bf(xa.z), xa.w - trunc_bf(xa.w));
        Xh[xrow][2 * xkq + 2] = pack_hi(xb.x, xb.y);
        Xh[xrow][2 * xkq + 3] = pack_hi(xb.z, xb.w);
        Xl[xrow][2 * xkq + 2] = pack_rn(xb.x - trunc_bf(xb.x), xb.y - trunc_bf(xb.y));
        Xl[xrow][2 * xkq + 3] = pack_rn(xb.z - trunc_bf(xb.z), xb.w - trunc_bf(xb.w));
        #pragma unroll
        for (int q = 0; q < 3; q++) {
            float4 wa = wva[q], wb = wvb[q];
            Wph[q][wkk][wn + 0] = pack_hi(wa.x, wb.x);
            Wph[q][wkk][wn + 1] = pack_hi(wa.y, wb.y);
            Wph[q][wkk][wn + 2] = pack_hi(wa.z, wb.z);
            Wph[q][wkk][wn + 3] = pack_hi(wa.w, wb.w);
            Wpl[q][wkk][wn + 0] = pack_rn(wa.x - trunc_bf(wa.x), wb.x - trunc_bf(wb.x));
            Wpl[q][wkk][wn + 1] = pack_rn(wa.y - trunc_bf(wa.y), wb.y - trunc_bf(wb.y));
            Wpl[q][wkk][wn + 2] = pack_rn(wa.z - trunc_bf(wa.z), wb.z - trunc_bf(wb.z));
            Wpl[q][wkk][wn + 3] = pack_rn(wa.w - trunc_bf(wa.w), wb.w - trunc_bf(wb.w));
        }
        __syncthreads();

        if (c < 63) {
            int k0 = (c + 1) * 16;
            xa = *(const float4*)&x[(size_t)(m0 + xrow) * Cc + k0 + xkq * 4];
            xb = *(const float4*)&x[(size_t)(m0 + xrow) * Cc + k0 + (xkq + 1) * 4];
            #pragma unroll
            for (int q = 0; q < 3; q++) {
                wva[q] = *(const float4*)&Ws[q][(size_t)(k0 + 2 * wkk) * Hh + wn];
                wvb[q] = *(const float4*)&Ws[q][(size_t)(k0 + 2 * wkk + 1) * Hh + wn];
            }
        }

        const int r = w * 16 + gid;
        unsigned a0h = Xh[r][tig],     a1h = Xh[r + 8][tig];
        unsigned a2h = Xh[r][tig + 4], a3h = Xh[r + 8][tig + 4];
        unsigned a0l = Xl[r][tig],     a1l = Xl[r + 8][tig];
        unsigned a2l = Xl[r][tig + 4], a3l = Xl[r + 8][tig + 4];

        #pragma unroll
        for (int q = 0; q < 3; q++)
            #pragma unroll
            for (int jn = 0; jn < 8; jn++) {
                int n = gid + 8 * jn;
                unsigned bh0 = Wph[q][tig][n], bh1 = Wph[q][tig + 4][n];
                unsigned bl0 = Wpl[q][tig][n], bl1 = Wpl[q][tig + 4][n];
                mma16816(acc[q][jn], a0h, a1h, a2h, a3h, bh0, bh1);
                mma16816(acc[q][jn], a0l, a1l, a2l, a3l, bh0, bh1);
                mma16816(acc[q][jn], a0h, a1h, a2h, a3h, bl0, bl1);
            }
        __syncthreads();
    }

    const int r0 = m0 + w * 16 + gid;
    // q (scaled 1/32) and k: [token][32] layout
    #pragma unroll
    for (int q = 0; q < 2; q++) {
        unsigned* __restrict__ OH = q ? g_kh : g_qh;
        unsigned* __restrict__ OL = q ? g_kl : g_ql;
        const float sc = q ? 1.0f : 0.03125f;
        #pragma unroll
        for (int jn = 0; jn < 8; jn++) {
            float c0 = acc[q][jn][0] * sc, c1 = acc[q][jn][1] * sc;
            float c2 = acc[q][jn][2] * sc, c3 = acc[q][jn][3] * sc;
            int p = 4 * jn + tig;
            OH[(size_t)r0 * 32 + p]       = pack_hi(c0, c1);
            OL[(size_t)r0 * 32 + p]       = pack_rn(c0 - trunc_bf(c0), c1 - trunc_bf(c1));
            OH[(size_t)(r0 + 8) * 32 + p] = pack_hi(c2, c3);
            OL[(size_t)(r0 + 8) * 32 + p] = pack_rn(c2 - trunc_bf(c2), c3 - trunc_bf(c3));
        }
    }
    // v: token-paired layout.  lanes (gid, gid^1) = adjacent token rows.
    #pragma unroll
    for (int jn = 0; jn < 8; jn++) {
        float c0 = acc[2][jn][0], c1 = acc[2][jn][1];
        float c2 = acc[2][jn][2], c3 = acc[2][jn][3];
        float d0 = __shfl_xor_sync(0xffffffffu, c0, 4);
        float d1 = __shfl_xor_sync(0xffffffffu, c1, 4);
        float d2 = __shfl_xor_sync(0xffffffffu, c2, 4);
        float d3 = __shfl_xor_sync(0xffffffffu, c3, 4);
        int p = 4 * jn + tig;
        size_t tp0 = (size_t)(r0 >> 1) * 64;
        size_t tp1 = (size_t)((r0 + 8) >> 1) * 64;
        if (!(gid & 1)) {       // even token row: write h = 2p
            g_vh[tp0 + 2 * p] = pack_hi(c0, d0);
            g_vl[tp0 + 2 * p] = pack_rn(c0 - trunc_bf(c0), d0 - trunc_bf(d0));
            g_vh[tp1 + 2 * p] = pack_hi(c2, d2);
            g_vl[tp1 + 2 * p] = pack_rn(c2 - trunc_bf(c2), d2 - trunc_bf(d2));
        } else {                // odd token row: write h = 2p+1
            g_vh[tp0 + 2 * p + 1] = pack_hi(d1, c1);
            g_vl[tp0 + 2 * p + 1] = pack_rn(d1 - trunc_bf(d1), c1 - trunc_bf(c1));
            g_vh[tp1 + 2 * p + 1] = pack_hi(d3, c3);
            g_vl[tp1 + 2 * p + 1] = pack_rn(d3 - trunc_bf(d3), c3 - trunc_bf(c3));
        }
    }
}

// ---------------------------------------------------------------------------
// Kernel 2: causal flash attention, split-KV 2-way, cp.async double-buffered.
// (unchanged from round 7 — verified at 221.9us total)
// ---------------------------------------------------------------------------
#define PK 36
#define PV 72
#define STG_U32 9216
#define ATTN_SMEM (2 * STG_U32 * 4)   // 73728 B

__global__ __launch_bounds__(128) void attn_kernel() {
    extern __shared__ unsigned smem[];

    const int b   = blockIdx.y;
    const int bx  = blockIdx.x;
    const int s   = bx & 1;
    const int qih = bx >> 1;
    const int qi  = (qih & 1) ? (63 - (qih >> 1)) : (qih >> 1);
    const int q0  = qi * 64;
    const int tid = threadIdx.x;
    const int w   = tid >> 5;
    const int lane = tid & 31;
    const int gid = lane >> 2;
    const int tig = lane & 3;

    const int half = (qi + 1) >> 1;
    const int kv0 = s ? half : 0;
    const int kv1 = s ? (qi + 1) : half;
    const int nt  = kv1 - kv0;

    float* __restrict__ op = g_op[s] + ((size_t)b * Tt + q0) * 64;

    if (nt == 0) {
        for (int i = tid; i < 64 * 64; i += 128) op[i] = 0.f;
        if (tid < 64) {
            g_m[s][(size_t)b * Tt + q0 + tid] = -1e30f;
            g_l[s][(size_t)b * Tt + q0 + tid] = 0.f;
        }
        return;
    }

    const unsigned* __restrict__ QH = g_qh + (size_t)b * Tt * 32;
    const unsigned* __restrict__ QL = g_ql + (size_t)b * Tt * 32;
    const unsigned* __restrict__ KH = g_kh + (size_t)b * Tt * 32;
    const unsigned* __restrict__ KL = g_kl + (size_t)b * Tt * 32;
    const unsigned* __restrict__ VH = g_vh + (size_t)b * (Tt / 2) * 64;
    const unsigned* __restrict__ VL = g_vl + (size_t)b * (Tt / 2) * 64;

    const unsigned smbase = (unsigned)__cvta_generic_to_shared(smem);

    const int kr = tid >> 3, kc = tid & 7;
    const int vr = tid >> 4, vc = tid & 15;

    #define PREFETCH(j) do {                                                    \
        const int kt__ = kv0 + (j);                                             \
        const unsigned bs__ = smbase + ((j) & 1) * (STG_U32 * 4);               \
        const int k0__ = kt__ * 64, kp__ = kt__ * 32;                           \
        _Pragma("unroll")                                                       \
        for (int i = 0; i < 4; i++) {                                           \
            int krr = kr + 16 * i;                                              \
            cpa16(bs__ + krr * 144 + kc * 16,          KH + (size_t)(k0__ + krr) * 32 + 4 * kc); \
            cpa16(bs__ + 9216 + krr * 144 + kc * 16,   KL + (size_t)(k0__ + krr) * 32 + 4 * kc); \
            int vrr = vr + 8 * i;                                               \
            cpa16(bs__ + 18432 + vrr * 288 + vc * 16,  VH + (size_t)(kp__ + vrr) * 64 + 4 * vc); \
            cpa16(bs__ + 27648 + vrr * 288 + vc * 16,  VL + (size_t)(kp__ + vrr) * 64 + 4 * vc); \
        }                                                                       \
        CP_COMMIT();                                                            \
    } while (0)

    unsigned qh[4][4], ql[4][4];
    {
        const int r0 = q0 + w * 16 + gid;
        #pragma unroll
        for (int c = 0; c < 4; c++) {
            qh[c][0] = QH[(size_t)r0 * 32 + 8 * c + tig];
            qh[c][1] = QH[(size_t)(r0 + 8) * 32 + 8 * c + tig];
            qh[c][2] = QH[(size_t)r0 * 32 + 8 * c + tig + 4];
            qh[c][3] = QH[(size_t)(r0 + 8) * 32 + 8 * c + tig + 4];
            ql[c][0] = QL[(size_t)r0 * 32 + 8 * c + tig];
            ql[c][1] = QL[(size_t)(r0 + 8) * 32 + 8 * c + tig];
            ql[c][2] = QL[(size_t)r0 * 32 + 8 * c + tig + 4];
            ql[c][3] = QL[(size_t)(r0 + 8) * 32 + 8 * c + tig + 4];
        }
    }

    PREFETCH(0);

    float o_acc[8][4];
    #pragma unroll
    for (int j = 0; j < 8; j++)
        #pragma unroll
        for (int e = 0; e < 4; e++) o_acc[j][e] = 0.f;
    float m0 = -1e30f, m1 = -1e30f;
    float l0 = 0.f, l1 = 0.f;

    for (int j = 0; j < nt; j++) {
        const int kt = kv0 + j;
        const int k0 = kt * 64;

        if (j + 1 < nt) { PREFETCH(j + 1); CP_WAIT(1); }
        else            { CP_WAIT(0); }
        __syncthreads();

        const unsigned* sKh = smem + (j & 1) * STG_U32;
        const unsigned* sKl = sKh + 2304;
        const unsigned* sVh = sKh + 4608;
        const unsigned* sVl = sKh + 6912;

        float sv[8][4];
        #pragma unroll
        for (int jn = 0; jn < 8; jn++) {
            sv[jn][0] = sv[jn][1] = sv[jn][2] = sv[jn][3] = 0.f;
            int n = gid + 8 * jn;
            #pragma unroll
            for (int c = 0; c < 4; c++) {
                unsigned bh0 = sKh[n * PK + 8 * c + tig];
                unsigned bh1 = sKh[n * PK + 8 * c + tig + 4];
                unsigned bl0 = sKl[n * PK + 8 * c + tig];
                unsigned bl1 = sKl[n * PK + 8 * c + tig + 4];
                mma16816(sv[jn], qh[c][0], qh[c][1], qh[c][2], qh[c][3], bh0, bh1);
                mma16816(sv[jn], ql[c][0], ql[c][1], ql[c][2], ql[c][3], bh0, bh1);
                mma16816(sv[jn], qh[c][0], qh[c][1], qh[c][2], qh[c][3], bl0, bl1);
            }
        }

        if (kt == qi) {
            const int r0g = q0 + w * 16 + gid, r1g = r0g + 8;
            #pragma unroll
            for (int jn = 0; jn < 8; jn++) {
                int col = k0 + 8 * jn + 2 * tig;
                if (col     > r0g) sv[jn][0] = -1e30f;
                if (col + 1 > r0g) sv[jn][1] = -1e30f;
                if (col     > r1g) sv[jn][2] = -1e30f;
                if (col + 1 > r1g) sv[jn][3] = -1e30f;
            }
        }

        float tm0 = -1e30f, tm1 = -1e30f;
        #pragma unroll
        for (int jn = 0; jn < 8; jn++) {
            tm0 = fmaxf(tm0, fmaxf(sv[jn][0], sv[jn][1]));
            tm1 = fmaxf(tm1, fmaxf(sv[jn][2], sv[jn][3]));
        }
        tm0 = fmaxf(tm0, __shfl_xor_sync(0xffffffffu, tm0, 1));
        tm0 = fmaxf(tm0, __shfl_xor_sync(0xffffffffu, tm0, 2));
        tm1 = fmaxf(tm1, __shfl_xor_sync(0xffffffffu, tm1, 1));
        tm1 = fmaxf(tm1, __shfl_xor_sync(0xffffffffu, tm1, 2));

        float mn0 = fmaxf(m0, tm0), mn1 = fmaxf(m1, tm1);
        float al0 = __expf(m0 - mn0), al1 = __expf(m1 - mn1);
        m0 = mn0; m1 = mn1;

        float rs0 = 0.f, rs1 = 0.f;
        #pragma unroll
        for (int jn = 0; jn < 8; jn++) {
            sv[jn][0] = __expf(sv[jn][0] - mn0);
            sv[jn][1] = __expf(sv[jn][1] - mn0);
            sv[jn][2] = __expf(sv[jn][2] - mn1);
            sv[jn][3] = __expf(sv[jn][3] - mn1);
            rs0 += sv[jn][0] + sv[jn][1];
            rs1 += sv[jn][2] + sv[jn][3];
        }
        l0 = l0 * al0 + rs0;
        l1 = l1 * al1 + rs1;
        #pragma unroll
        for (int jn = 0; jn < 8; jn++) {
            o_acc[jn][0] *= al0; o_acc[jn][1] *= al0;
            o_acc[jn][2] *= al1; o_acc[jn][3] *= al1;
        }

        #pragma unroll
        for (int jp = 0; jp < 4; jp++) {
            unsigned p0h = pack_hi(sv[2 * jp][0], sv[2 * jp][1]);
            unsigned p1h = pack_hi(sv[2 * jp][2], sv[2 * jp][3]);
            unsigned p2h = pack_hi(sv[2 * jp + 1][0], sv[2 * jp + 1][1]);
            unsigned p3h = pack_hi(sv[2 * jp + 1][2], sv[2 * jp + 1][3]);
            unsigned p0l = pack_rn(sv[2 * jp][0] - trunc_bf(sv[2 * jp][0]),
                                   sv[2 * jp][1] - trunc_bf(sv[2 * jp][1]));
            unsigned p1l = pack_rn(sv[2 * jp][2] - trunc_bf(sv[2 * jp][2]),
                                   sv[2 * jp][3] - trunc_bf(sv[2 * jp][3]));
            unsigned p2l = pack_rn(sv[2 * jp + 1][0] - trunc_bf(sv[2 * jp + 1][0]),
                                   sv[2 * jp + 1][1] - trunc_bf(sv[2 * jp + 1][1]));
            unsigned p3l = pack_rn(sv[2 * jp + 1][2] - trunc_bf(sv[2 * jp + 1][2]),
                                   sv[2 * jp + 1][3] - trunc_bf(sv[2 * jp + 1][3]));
            #pragma unroll
            for (int jn = 0; jn < 8; jn++) {
                int n = gid + 8 * jn;
                unsigned bh0 = sVh[(8 * jp + tig) * PV + n];
                unsigned bh1 = sVh[(8 * jp + tig + 4) * PV + n];
                unsigned bl0 = sVl[(8 * jp + tig) * PV + n];
                unsigned bl1 = sVl[(8 * jp + tig + 4) * PV + n];
                mma16816(o_acc[jn], p0h, p1h, p2h, p3h, bh0, bh1);
                mma16816(o_acc[jn], p0l, p1l, p2l, p3l, bh0, bh1);
                mma16816(o_acc[jn], p0h, p1h, p2h, p3h, bl0, bl1);
            }
        }
        __syncthreads();
    }

    l0 += __shfl_xor_sync(0xffffffffu, l0, 1);
    l0 += __shfl_xor_sync(0xffffffffu, l0, 2);
    l1 += __shfl_xor_sync(0xffffffffu, l1, 1);
    l1 += __shfl_xor_sync(0xffffffffu, l1, 2);

    const int rloc = w * 16 + gid;
    if (tig == 0) {
        g_m[s][(size_t)b * Tt + q0 + rloc]     = m0;
        g_l[s][(size_t)b * Tt + q0 + rloc]     = l0;
        g_m[s][(size_t)b * Tt + q0 + rloc + 8] = m1;
        g_l[s][(size_t)b * Tt + q0 + rloc + 8] = l1;
    }
    #pragma unroll
    for (int jn = 0; jn < 8; jn++) {
        int n = 8 * jn + 2 * tig;
        *(float2*)&op[(size_t)rloc * 64 + n]       = make_float2(o_acc[jn][0], o_acc[jn][1]);
        *(float2*)&op[(size_t)(rloc + 8) * 64 + n] = make_float2(o_acc[jn][2], o_acc[jn][3]);
    }
}

// ---------------------------------------------------------------------------
// Kernel 3: combine the two KV splits.
// ---------------------------------------------------------------------------
__global__ __launch_bounds__(256) void combine_kernel(float* __restrict__ o) {
    int idx = blockIdx.x * 256 + threadIdx.x;
    int row = idx >> 6;
    float m0 = g_m[0][row], m1 = g_m[1][row];
    float l0 = g_l[0][row], l1 = g_l[1][row];
    float mx = fmaxf(m0, m1);
    float w0 = __expf(m0 - mx), w1 = __expf(m1 - mx);
    float inv = 1.0f / (w0 * l0 + w1 * l1);
    o[idx] = (w0 * g_op[0][idx] + w1 * g_op[1][idx]) * inv;
}

// ---------------------------------------------------------------------------
extern "C" void kernel_launch(void* const* d_in, const int* in_sizes, int n_in,
                              void* d_out, int out_size) {
    const float* x  = (const float*)d_in[0];
    const float* Wq = (const float*)d_in[1];
    const float* Wk = (const float*)d_in[2];
    const float* Wv = (const float*)d_in[3];
    float* out = (float*)d_out;

    qkv_gemm<<<dim3(BT / 64, 1), 128>>>(x, Wq, Wk, Wv);

    cudaFuncSetAttribute(attn_kernel,
                         cudaFuncAttributeMaxDynamicSharedMemorySize, ATTN_SMEM);
    attn_kernel<<<dim3(128, Bsz), 128, ATTN_SMEM>>>();

    combine_kernel<<<BT * 64 / 256, 256>>>(out);
}